// round 13
// baseline (speedup 1.0000x reference)
#include <cuda_runtime.h>
#include <cstdint>

#define BATCH  32
#define SEQ    512
#define LAB    64
#define START_ 61
#define STOP_  62
#define CH     32

#define FMA2(d,a,b,c)  asm("fma.rn.f32x2 %0, %1, %2, %3;" : "=l"(d) : "l"(a), "l"(b), "l"(c))
#define ADD2(d,a,b)    asm("add.rn.f32x2 %0, %1, %2;"     : "=l"(d) : "l"(a), "l"(b))
#define PACK2(d,lo,hi) asm("mov.b64 %0, {%1, %2};"        : "=l"(d) : "f"(lo), "f"(hi))
#define UNPACK2(lo,hi,s) asm("mov.b64 {%0, %1}, %2;"      : "=f"(lo), "=f"(hi) : "l"(s))
#define CPA(dst,src) asm volatile("cp.async.cg.shared.global [%0], [%1], 16;\n" :: "r"(dst), "l"(src))
#define CPC() asm volatile("cp.async.commit_group;\n")
#define CPW1() asm volatile("cp.async.wait_group 1;\n")
#define CPW0() asm volatile("cp.async.wait_group 0;\n")
// per-half 64-thread named barrier: id 1 for half 0, id 2 for half 1
#define BARC() asm volatile("bar.sync %0, 64;" :: "r"(barid) : "memory")

// 64-thread chunk prefetch into this half's buffer: 8 KB
#define PREFETCH(cc) do {                                                        \
    const float* _src = encb + (size_t)(cc) * CH * LAB + ltid * 4;               \
    uint32_t _dst = (uint32_t)__cvta_generic_to_shared(&esh[(cc) & 1][ltid*4]);  \
    CPA(_dst,        _src);         CPA(_dst + 1024, _src + 256);                \
    CPA(_dst + 2048, _src + 512);   CPA(_dst + 3072, _src + 768);                \
    CPA(_dst + 4096, _src + 1024);  CPA(_dst + 5120, _src + 1280);               \
    CPA(_dst + 6144, _src + 1536);  CPA(_dst + 7168, _src + 1792);               \
    CPC();                                                                       \
} while (0)

// full 64-wide dot per thread: 16 broadcast LDS.128 + 32 FMA2 + tree
#define DOT64(PV, Q)                                                          \
    ulonglong2 w0 = (PV)[0],  w1 = (PV)[1],  w2 = (PV)[2],  w3 = (PV)[3];     \
    ulonglong2 w4 = (PV)[4],  w5 = (PV)[5],  w6 = (PV)[6],  w7 = (PV)[7];     \
    ulonglong2 w8 = (PV)[8],  w9 = (PV)[9],  wA = (PV)[10], wB = (PV)[11];    \
    ulonglong2 wC = (PV)[12], wD = (PV)[13], wE = (PV)[14], wF = (PV)[15];    \
    unsigned long long a0 = 0, a1 = 0, a2 = 0, a3 = 0;                        \
    FMA2(a0, w0.x, E2[ 0], a0); FMA2(a1, w0.y, E2[ 1], a1);                   \
    FMA2(a2, w1.x, E2[ 2], a2); FMA2(a3, w1.y, E2[ 3], a3);                   \
    FMA2(a0, w2.x, E2[ 4], a0); FMA2(a1, w2.y, E2[ 5], a1);                   \
    FMA2(a2, w3.x, E2[ 6], a2); FMA2(a3, w3.y, E2[ 7], a3);                   \
    FMA2(a0, w4.x, E2[ 8], a0); FMA2(a1, w4.y, E2[ 9], a1);                   \
    FMA2(a2, w5.x, E2[10], a2); FMA2(a3, w5.y, E2[11], a3);                   \
    FMA2(a0, w6.x, E2[12], a0); FMA2(a1, w6.y, E2[13], a1);                   \
    FMA2(a2, w7.x, E2[14], a2); FMA2(a3, w7.y, E2[15], a3);                   \
    FMA2(a0, w8.x, E2[16], a0); FMA2(a1, w8.y, E2[17], a1);                   \
    FMA2(a2, w9.x, E2[18], a2); FMA2(a3, w9.y, E2[19], a3);                   \
    FMA2(a0, wA.x, E2[20], a0); FMA2(a1, wA.y, E2[21], a1);                   \
    FMA2(a2, wB.x, E2[22], a2); FMA2(a3, wB.y, E2[23], a3);                   \
    FMA2(a0, wC.x, E2[24], a0); FMA2(a1, wC.y, E2[25], a1);                   \
    FMA2(a2, wD.x, E2[26], a2); FMA2(a3, wD.y, E2[27], a3);                   \
    FMA2(a0, wE.x, E2[28], a0); FMA2(a1, wE.y, E2[29], a1);                   \
    FMA2(a2, wF.x, E2[30], a2); FMA2(a3, wF.y, E2[31], a3);                   \
    unsigned long long s01, s23, sT;                                          \
    ADD2(s01, a0, a1); ADD2(s23, a2, a3); ADD2(sT, s01, s23);                 \
    float qlo, qhi; UNPACK2(qlo, qhi, sT);                                    \
    float Q = qlo + qhi

// chains per batch: 0=x(seg1) 1=f2 2=f3 3=f4 4=g2 5=g3 6=g4 7=y(seg5)
__device__ float g_v[8][BATCH][LAB];
__device__ float g_lab[4][BATCH];
__device__ int   g_mi8[8][BATCH];
__device__ int   g_cnt[BATCH];     // never reset; +4 per launch; (old&3)==3 -> combiner

__global__ __launch_bounds__(128, 1)
void crf_fused_kernel(const float* __restrict__ enc,   // [B,S,L]
                      const float* __restrict__ T,     // [L,L]
                      const int*   __restrict__ lens,  // [B]
                      const int*   __restrict__ tags,  // [B,S]
                      float*       __restrict__ out)   // [2*B]
{
    // [half][buf] enc chunks; [half][buf] state
    __shared__ __align__(16) float e_sh2[2][2][CH * LAB];
    __shared__ __align__(16) float p_sh2[2][2][LAB];
    __shared__ float lw[4];
    __shared__ float du[14];
    __shared__ int win_sh;

    const int tid  = threadIdx.x;
    const int half = tid >> 6;            // chain slot within block
    const int ltid = tid & 63;            // column index within chain
    const int barid = 1 + half;

    const int b    = blockIdx.x >> 2;
    const int pair = blockIdx.x & 3;
    const int k    = 2 * pair + half;     // chain id 0..7
    const int len  = lens[b];
    const int n    = len - 1;
    int sB[6];
    #pragma unroll
    for (int i = 0; i <= 5; ++i) sB[i] = (i * n) / 5;
    const float* encb = enc + (size_t)b * SEQ * LAB;
    const int*   tagb = tags + b * SEQ;

    float (*esh)[CH * LAB] = e_sh2[half];
    float (*psh)[LAB]      = p_sh2[half];

    int Mi = 0;
    int par_out;

    if (k <= 3) {
        // ---- FORWARD chains: p <- D_u E^T p over seg k+1 = (sB[k], sB[k+1]] ----
        const int t0 = sB[k] + 1;
        const int t1 = sB[k + 1];

        unsigned long long E2[32];                     // E column ltid, all 64 rows
        #pragma unroll
        for (int kk = 0; kk < 32; ++kk) {
            float lo = expf(T[(2 * kk)     * LAB + ltid]);
            float hi = expf(T[(2 * kk + 1) * LAB + ltid]);
            PACK2(E2[kk], lo, hi);
        }

        const int c0 = t0 >> 5, c1 = t1 >> 5;
        PREFETCH(c0);
        if (c0 < c1) { PREFETCH(c0 + 1); CPW1(); } else CPW0();
        BARC();
        if (k == 0) psh[0][ltid] = expf(T[START_ * LAB + ltid] + esh[0][ltid]);
        else        psh[(t0 - 1) & 1][ltid] = 1.0f;    // probe: ones
        BARC();

        int t = t0;
        for (int c = c0; c <= c1; ++c) {
            if (c > c0) {
                if (c < c1) { PREFETCH(c + 1); CPW1(); } else CPW0();
                BARC();
            }
            const float* eb = esh[c & 1];
            const int ttend = min((c + 1) * CH - 1, t1);
            #pragma unroll 4
            for (; t <= ttend; ++t) {
                const float* pp = &psh[(t - 1) & 1][0];
                const ulonglong2* pv = reinterpret_cast<const ulonglong2*>(pp);
                float u  = __expf(eb[(t - c * CH) * LAB + ltid]);
                DOT64(pv, q);
                unsigned int p0b = (unsigned int)w0.x;     // p[0], broadcast-uniform
                int   e0 = (int)((p0b >> 23) & 255u) - 127;
                float sc = __int_as_float((127 - e0) << 23);
                Mi += e0;
                psh[t & 1][ltid] = q * u * sc;
                BARC();
            }
        }
        par_out = t1 & 1;
    } else {
        // ---- BACKWARD chains: w <- D_u E w over seg sg = (sB[sg-1], sB[sg]] ----
        const int sg = k - 2;                          // 2,3,4,5
        const int s_init = sB[sg];
        const int s_end  = sB[sg - 1];
        const int s1 = s_init - 1, s0 = s_end;

        unsigned long long E2[32];                     // E row ltid, all 64 cols
        #pragma unroll
        for (int kk = 0; kk < 32; ++kk) {
            float lo = expf(T[ltid * LAB + 2 * kk]);
            float hi = expf(T[ltid * LAB + 2 * kk + 1]);
            PACK2(E2[kk], lo, hi);
        }

        const int chi = s1 >> 5, clo = s0 >> 5;
        PREFETCH(chi);
        if (chi > clo) PREFETCH(chi - 1);
        {
            float uinit = __expf(encb[(size_t)s_init * LAB + ltid]);
            if (sg == 5) uinit *= expf(T[ltid * LAB + STOP_]);  // y: c * u_n
            psh[(s1 + 1) & 1][ltid] = uinit;
        }
        if (chi > clo) CPW1(); else CPW0();
        BARC();

        int s = s1;
        for (int c = chi; c >= clo; --c) {
            if (c < chi) {
                if (c > clo) { PREFETCH(c - 1); CPW1(); } else CPW0();
                BARC();
            }
            const float* eb = esh[c & 1];
            const int slo = max(s0, c * CH);
            #pragma unroll 4
            for (; s >= slo; --s) {
                const float* pp = &psh[(s + 1) & 1][0];
                const ulonglong2* pv = reinterpret_cast<const ulonglong2*>(pp);
                float u  = __expf(eb[(s - c * CH) * LAB + ltid]);
                DOT64(pv, q);
                unsigned int p0b = (unsigned int)w0.x;
                int   e0 = (int)((p0b >> 23) & 255u) - 127;
                float sc = __int_as_float((127 - e0) << 23);
                Mi += e0;
                float us = (s == s0) ? sc : u * sc;    // boundary: apply E only
                psh[s & 1][ltid] = q * us;
                BARC();
            }
        }
        par_out = s0 & 1;
    }

    g_v[k][b][ltid] = psh[par_out][ltid];
    if (ltid == 0) g_mi8[k][b] = Mi;
    __syncthreads();                       // both halves done

    // ---- labeled partial for this block's quarter of [1, n] ----
    {
        const int lo = 1 + (pair * n) / 4;
        const int hi = 1 + ((pair + 1) * n) / 4;
        float lsum = 0.0f;
        for (int t = lo + tid; t < hi; t += 128) {
            int tg = tagb[t], tp = tagb[t - 1];
            lsum += T[tp * LAB + tg] + encb[(size_t)t * LAB + tg];
        }
        #pragma unroll
        for (int m = 16; m; m >>= 1)
            lsum += __shfl_xor_sync(0xffffffffu, lsum, m);
        if ((tid & 31) == 0) lw[tid >> 5] = lsum;
        __syncthreads();
        if (tid == 0) g_lab[pair][b] = lw[0] + lw[1] + lw[2] + lw[3];
    }

    // ---- last-arriver combine ----
    __threadfence();
    __syncthreads();
    if (tid == 0) {
        int old = atomicAdd(&g_cnt[b], 1);
        win_sh = ((old & 3) == 3);
    }
    __syncthreads();
    if (win_sh) {
        float d1 = 0, d2 = 0, d3 = 0, d4 = 0, d5 = 0, d6 = 0, d7 = 0;
        if (tid < LAB) {
            float xv  = __ldcg(&g_v[0][b][tid]);
            float f2v = __ldcg(&g_v[1][b][tid]);
            float f3v = __ldcg(&g_v[2][b][tid]);
            float f4v = __ldcg(&g_v[3][b][tid]);
            float g2v = __ldcg(&g_v[4][b][tid]);
            float g3v = __ldcg(&g_v[5][b][tid]);
            float g4v = __ldcg(&g_v[6][b][tid]);
            float yv  = __ldcg(&g_v[7][b][tid]);
            d1 = yv  * f4v;    // c^T M5 f4
            d2 = g4v * f3v;
            d3 = g3v * f2v;
            d4 = g2v * xv;     // g2^T M1 p0
            d5 = f2v; d6 = f3v; d7 = f4v;
        }
        #pragma unroll
        for (int m = 16; m; m >>= 1) {
            d1 += __shfl_xor_sync(0xffffffffu, d1, m);
            d2 += __shfl_xor_sync(0xffffffffu, d2, m);
            d3 += __shfl_xor_sync(0xffffffffu, d3, m);
            d4 += __shfl_xor_sync(0xffffffffu, d4, m);
            d5 += __shfl_xor_sync(0xffffffffu, d5, m);
            d6 += __shfl_xor_sync(0xffffffffu, d6, m);
            d7 += __shfl_xor_sync(0xffffffffu, d7, m);
        }
        if (tid == 0) {
            du[0]=d1; du[1]=d2; du[2]=d3; du[3]=d4; du[4]=d5; du[5]=d6; du[6]=d7;
        }
        if (tid == 32) {
            du[7]=d1; du[8]=d2; du[9]=d3; du[10]=d4; du[11]=d5; du[12]=d6; du[13]=d7;
        }
        __syncthreads();
        if (tid == 0) {
            float D1 = du[0] + du[7];
            float D2 = du[1] + du[8];
            float D3 = du[2] + du[9];
            float D4 = du[3] + du[10];
            float S2 = du[4] + du[11];
            float S3 = du[5] + du[12];
            float S4 = du[6] + du[13];
            int mtot = __ldcg(&g_mi8[0][b]) + __ldcg(&g_mi8[4][b])
                     + __ldcg(&g_mi8[5][b]) + __ldcg(&g_mi8[6][b])
                     + __ldcg(&g_mi8[7][b]);
            double lg = (double)logf(D1) + (double)logf(D2)
                      + (double)logf(D3) + (double)logf(D4)
                      - (double)logf(S2) - (double)logf(S3) - (double)logf(S4);
            out[b] = (float)((double)mtot * 0.6931471805599453 + lg);

            int t0g = tagb[0];
            int eg  = tagb[len - 1];
            out[BATCH + b] = __ldcg(&g_lab[0][b]) + __ldcg(&g_lab[1][b])
                           + __ldcg(&g_lab[2][b]) + __ldcg(&g_lab[3][b])
                           + T[START_ * LAB + t0g] + encb[t0g]
                           + T[eg * LAB + STOP_];
        }
    }
}

extern "C" void kernel_launch(void* const* d_in, const int* in_sizes, int n_in,
                              void* d_out, int out_size)
{
    const float* enc  = (const float*)d_in[0];   // encoder_scores [32,512,64]
    const float* T    = (const float*)d_in[1];   // transition [64,64]
    const int*   lens = (const int*)  d_in[2];   // word_seq_lens [32]
    const int*   tags = (const int*)  d_in[3];   // tags [32,512]
    float* out = (float*)d_out;                  // [64]: unlabeled(32) ++ labeled(32)

    crf_fused_kernel<<<4 * BATCH, 128>>>(enc, T, lens, tags, out);
}